// round 1
// baseline (speedup 1.0000x reference)
#include <cuda_runtime.h>
#include <math.h>

#define BATCH 2
#define SEQ   2048
#define HID   4096
#define NH    32
#define NKV   8
#define HD    128
#define GQA   4
#define NQ    (NH*HD)     // 4096
#define NKN   (NKV*HD)    // 1024
#define MTOT  (BATCH*SEQ) // 4096

// Scratch (no allocations allowed)
__device__ float g_q[(size_t)BATCH*NH*SEQ*HD];
__device__ float g_k[(size_t)BATCH*NKV*SEQ*HD];
__device__ float g_v[(size_t)BATCH*NKV*SEQ*HD];
__device__ float g_attn[(size_t)BATCH*SEQ*NH*HD];

// ---------------------------------------------------------------------------
// Kernel 1: fused QKV projection (C = X @ W^T) with RoPE epilogue for Q and K.
// X: [4096, 4096] row-major. Weights row-major [out, in].
// Output layouts: g_q [b, h, s, d], g_k/g_v [b, kv, s, d].
// Tiling: 64x64x32, 256 threads, 4x4 per-thread microtile.
// ---------------------------------------------------------------------------
__global__ __launch_bounds__(256) void qkv_kernel(
    const float* __restrict__ X,
    const float* __restrict__ Wq,
    const float* __restrict__ Wk,
    const float* __restrict__ Wv,
    const float* __restrict__ cosb,
    const float* __restrict__ sinb)
{
    __shared__ float As[32][68];
    __shared__ float Bs[32][68];

    const int tid = threadIdx.x;
    const int tx = tid & 15;
    const int ty = tid >> 4;
    const int m0 = blockIdx.y * 64;
    const int n0 = blockIdx.x * 64;

    const float* Wm;
    int nw;
    if (n0 < NQ)            { Wm = Wq; nw = n0; }
    else if (n0 < NQ + NKN) { Wm = Wk; nw = n0 - NQ; }
    else                    { Wm = Wv; nw = n0 - NQ - NKN; }

    float acc[4][4];
#pragma unroll
    for (int i = 0; i < 4; i++)
#pragma unroll
        for (int j = 0; j < 4; j++) acc[i][j] = 0.0f;

    for (int k0 = 0; k0 < HID; k0 += 32) {
#pragma unroll
        for (int f = 0; f < 2; f++) {
            int id  = tid + f * 256;
            int row = id >> 3;
            int kq  = (id & 7) << 2;
            float4 av = *reinterpret_cast<const float4*>(&X[(size_t)(m0 + row) * HID + k0 + kq]);
            As[kq + 0][row] = av.x; As[kq + 1][row] = av.y;
            As[kq + 2][row] = av.z; As[kq + 3][row] = av.w;
            float4 bv = *reinterpret_cast<const float4*>(&Wm[(size_t)(nw + row) * HID + k0 + kq]);
            Bs[kq + 0][row] = bv.x; Bs[kq + 1][row] = bv.y;
            Bs[kq + 2][row] = bv.z; Bs[kq + 3][row] = bv.w;
        }
        __syncthreads();
#pragma unroll
        for (int kk = 0; kk < 32; kk++) {
            float4 a4 = *reinterpret_cast<const float4*>(&As[kk][ty * 4]);
            float4 b4 = *reinterpret_cast<const float4*>(&Bs[kk][tx * 4]);
            float a[4] = {a4.x, a4.y, a4.z, a4.w};
            float b[4] = {b4.x, b4.y, b4.z, b4.w};
#pragma unroll
            for (int i = 0; i < 4; i++)
#pragma unroll
                for (int j = 0; j < 4; j++) acc[i][j] = fmaf(a[i], b[j], acc[i][j]);
        }
        __syncthreads();
    }

    // Epilogue with RoPE (pairs (even, odd) live inside one thread: 4 cols aligned to 4)
#pragma unroll
    for (int i = 0; i < 4; i++) {
        int m = m0 + ty * 4 + i;
        int b = m / SEQ;
        int s = m % SEQ;
#pragma unroll
        for (int jp = 0; jp < 2; jp++) {
            int j0 = jp * 2;
            int nn = n0 + tx * 4 + j0;   // even global col
            float v0 = acc[i][j0];
            float v1 = acc[i][j0 + 1];
            if (n0 < NQ) {
                int h = nn / HD, d = nn % HD;
                float c  = cosb[s * HD + d];
                float sn = sinb[s * HD + d];
                size_t base = (((size_t)b * NH + h) * SEQ + s) * HD + d;
                g_q[base]     = v0 * c - v1 * sn;
                g_q[base + 1] = v1 * c + v0 * sn;
            } else if (n0 < NQ + NKN) {
                int ln = nn - NQ;
                int h = ln / HD, d = ln % HD;
                float c  = cosb[s * HD + d];
                float sn = sinb[s * HD + d];
                size_t base = (((size_t)b * NKV + h) * SEQ + s) * HD + d;
                g_k[base]     = v0 * c - v1 * sn;
                g_k[base + 1] = v1 * c + v0 * sn;
            } else {
                int ln = nn - NQ - NKN;
                int h = ln / HD, d = ln % HD;
                size_t base = (((size_t)b * NKV + h) * SEQ + s) * HD + d;
                g_v[base]     = v0;
                g_v[base + 1] = v1;
            }
        }
    }
}

// ---------------------------------------------------------------------------
// Kernel 2: fp32 causal flash attention with GQA (4 q-heads per kv-head).
// One CTA per (q-block of 64, head, batch). 256 threads.
// Dynamic smem: Qs^T[128][68], Ks^T[128][68], Vs[64][132], Ps[64][68].
// ---------------------------------------------------------------------------
__device__ __forceinline__ void load_tile_T(const float* __restrict__ gsrc,
                                            float* __restrict__ dst,
                                            int row0, float mul, int tid)
{
    // gsrc rows of 128 floats; write transposed dst[c*68 + r], r in [0,64), c in [0,128)
    int lane = tid & 31;
    int warp = tid >> 5;
#pragma unroll
    for (int t = 0; t < 8; t++) {
        int unit = warp + t * 8;      // 0..63
        int rg   = unit & 15;         // row group (4 rows)
        int cg   = unit >> 4;         // col group (32 cols)
        int c    = cg * 32 + lane;
        const float* gp = gsrc + (size_t)(row0 + rg * 4) * HD + c;
        float v0 = gp[0]   * mul;
        float v1 = gp[HD]  * mul;
        float v2 = gp[2*HD]* mul;
        float v3 = gp[3*HD]* mul;
        *reinterpret_cast<float4*>(dst + c * 68 + rg * 4) = make_float4(v0, v1, v2, v3);
    }
}

__global__ __launch_bounds__(256) void attn_kernel()
{
    extern __shared__ float sm[];
    float* Qs = sm;                   // 128*68
    float* Ks = Qs + 128 * 68;        // 128*68
    float* Vs = Ks + 128 * 68;        // 64*132
    float* Ps = Vs + 64 * 132;        // 64*68

    const int tid = threadIdx.x;
    const int tx = tid & 15;
    const int ty = tid >> 4;
    const int q0 = blockIdx.x * 64;
    const int h  = blockIdx.y;
    const int b  = blockIdx.z;
    const int kvh = h / GQA;

    const float scale = 0.08838834764831845f;  // 1/sqrt(128)
    const float* qptr = g_q + (((size_t)b * NH  + h)   * SEQ) * HD;
    const float* kptr = g_k + (((size_t)b * NKV + kvh) * SEQ) * HD;
    const float* vptr = g_v + (((size_t)b * NKV + kvh) * SEQ) * HD;

    load_tile_T(qptr, Qs, q0, scale, tid);

    float acc[4][8];
#pragma unroll
    for (int i = 0; i < 4; i++)
#pragma unroll
        for (int j = 0; j < 8; j++) acc[i][j] = 0.0f;
    float mi[4], li[4];
#pragma unroll
    for (int i = 0; i < 4; i++) { mi[i] = -1e30f; li[i] = 0.0f; }

    const int nkb = q0 / 64 + 1;
    for (int kb = 0; kb < nkb; kb++) {
        const int k0 = kb * 64;
        load_tile_T(kptr, Ks, k0, 1.0f, tid);
        // V natural layout
#pragma unroll
        for (int t = 0; t < 8; t++) {
            int id = tid + t * 256;
            int r  = id >> 5;
            int c4 = (id & 31) << 2;
            float4 vv = *reinterpret_cast<const float4*>(&vptr[(size_t)(k0 + r) * HD + c4]);
            *reinterpret_cast<float4*>(&Vs[r * 132 + c4]) = vv;
        }
        __syncthreads();

        // Scores: 64x64, 4x4 per thread
        float sc[4][4];
#pragma unroll
        for (int i = 0; i < 4; i++)
#pragma unroll
            for (int j = 0; j < 4; j++) sc[i][j] = 0.0f;

#pragma unroll 8
        for (int d = 0; d < 128; d++) {
            float4 a4 = *reinterpret_cast<const float4*>(&Qs[d * 68 + ty * 4]);
            float4 b4 = *reinterpret_cast<const float4*>(&Ks[d * 68 + tx * 4]);
            float a[4] = {a4.x, a4.y, a4.z, a4.w};
            float bb[4] = {b4.x, b4.y, b4.z, b4.w};
#pragma unroll
            for (int i = 0; i < 4; i++)
#pragma unroll
                for (int j = 0; j < 4; j++) sc[i][j] = fmaf(a[i], bb[j], sc[i][j]);
        }

        const bool diag = (kb == nkb - 1);
#pragma unroll
        for (int i = 0; i < 4; i++) {
            int qi = q0 + ty * 4 + i;
            float rm = -1e30f;
#pragma unroll
            for (int j = 0; j < 4; j++) {
                if (diag) {
                    int kj = k0 + tx * 4 + j;
                    if (kj > qi) sc[i][j] = -1e30f;
                }
                rm = fmaxf(rm, sc[i][j]);
            }
#pragma unroll
            for (int off = 8; off >= 1; off >>= 1)
                rm = fmaxf(rm, __shfl_xor_sync(0xffffffffu, rm, off));
            float nm = fmaxf(mi[i], rm);
            float f  = __expf(mi[i] - nm);
            float rs = 0.0f;
#pragma unroll
            for (int j = 0; j < 4; j++) {
                float p = __expf(sc[i][j] - nm);
                sc[i][j] = p;
                rs += p;
            }
#pragma unroll
            for (int off = 8; off >= 1; off >>= 1)
                rs += __shfl_xor_sync(0xffffffffu, rs, off);
            li[i] = li[i] * f + rs;
            mi[i] = nm;
#pragma unroll
            for (int j = 0; j < 8; j++) acc[i][j] *= f;
            *reinterpret_cast<float4*>(&Ps[(ty * 4 + i) * 68 + tx * 4]) =
                make_float4(sc[i][0], sc[i][1], sc[i][2], sc[i][3]);
        }
        __syncthreads();

        // O += P @ V : 64x128 output, 4x8 per thread
#pragma unroll 4
        for (int kk = 0; kk < 64; kk++) {
            float p[4];
#pragma unroll
            for (int i = 0; i < 4; i++) p[i] = Ps[(ty * 4 + i) * 68 + kk];
            float4 v0 = *reinterpret_cast<const float4*>(&Vs[kk * 132 + tx * 8]);
            float4 v1 = *reinterpret_cast<const float4*>(&Vs[kk * 132 + tx * 8 + 4]);
            float v[8] = {v0.x, v0.y, v0.z, v0.w, v1.x, v1.y, v1.z, v1.w};
#pragma unroll
            for (int i = 0; i < 4; i++)
#pragma unroll
                for (int j = 0; j < 8; j++) acc[i][j] = fmaf(p[i], v[j], acc[i][j]);
        }
        __syncthreads();
    }

    // Writeback to [b, s, H*D]
#pragma unroll
    for (int i = 0; i < 4; i++) {
        int qi = q0 + ty * 4 + i;
        float inv = 1.0f / li[i];
        float* op = g_attn + ((size_t)b * SEQ + qi) * (NH * HD) + h * HD + tx * 8;
        *reinterpret_cast<float4*>(op) =
            make_float4(acc[i][0]*inv, acc[i][1]*inv, acc[i][2]*inv, acc[i][3]*inv);
        *reinterpret_cast<float4*>(op + 4) =
            make_float4(acc[i][4]*inv, acc[i][5]*inv, acc[i][6]*inv, acc[i][7]*inv);
    }
}

// ---------------------------------------------------------------------------
// Kernel 3: output projection out = attn @ wo^T  (4096 x 4096 x 4096)
// ---------------------------------------------------------------------------
__global__ __launch_bounds__(256) void oproj_kernel(
    const float* __restrict__ Wo, float* __restrict__ out)
{
    __shared__ float As[32][68];
    __shared__ float Bs[32][68];

    const int tid = threadIdx.x;
    const int tx = tid & 15;
    const int ty = tid >> 4;
    const int m0 = blockIdx.y * 64;
    const int n0 = blockIdx.x * 64;

    float acc[4][4];
#pragma unroll
    for (int i = 0; i < 4; i++)
#pragma unroll
        for (int j = 0; j < 4; j++) acc[i][j] = 0.0f;

    for (int k0 = 0; k0 < HID; k0 += 32) {
#pragma unroll
        for (int f = 0; f < 2; f++) {
            int id  = tid + f * 256;
            int row = id >> 3;
            int kq  = (id & 7) << 2;
            float4 av = *reinterpret_cast<const float4*>(&g_attn[(size_t)(m0 + row) * HID + k0 + kq]);
            As[kq + 0][row] = av.x; As[kq + 1][row] = av.y;
            As[kq + 2][row] = av.z; As[kq + 3][row] = av.w;
            float4 bv = *reinterpret_cast<const float4*>(&Wo[(size_t)(n0 + row) * HID + k0 + kq]);
            Bs[kq + 0][row] = bv.x; Bs[kq + 1][row] = bv.y;
            Bs[kq + 2][row] = bv.z; Bs[kq + 3][row] = bv.w;
        }
        __syncthreads();
#pragma unroll
        for (int kk = 0; kk < 32; kk++) {
            float4 a4 = *reinterpret_cast<const float4*>(&As[kk][ty * 4]);
            float4 b4 = *reinterpret_cast<const float4*>(&Bs[kk][tx * 4]);
            float a[4] = {a4.x, a4.y, a4.z, a4.w};
            float b[4] = {b4.x, b4.y, b4.z, b4.w};
#pragma unroll
            for (int i = 0; i < 4; i++)
#pragma unroll
                for (int j = 0; j < 4; j++) acc[i][j] = fmaf(a[i], b[j], acc[i][j]);
        }
        __syncthreads();
    }

#pragma unroll
    for (int i = 0; i < 4; i++) {
        int m = m0 + ty * 4 + i;
        float* op = out + (size_t)m * HID + n0 + tx * 4;
        *reinterpret_cast<float4*>(op) = make_float4(acc[i][0], acc[i][1], acc[i][2], acc[i][3]);
    }
}

// ---------------------------------------------------------------------------
extern "C" void kernel_launch(void* const* d_in, const int* in_sizes, int n_in,
                              void* d_out, int out_size)
{
    const float* hidden = (const float*)d_in[0];
    const float* cosb   = (const float*)d_in[1];
    const float* sinb   = (const float*)d_in[2];
    const float* wq     = (const float*)d_in[3];
    const float* wk     = (const float*)d_in[4];
    const float* wv     = (const float*)d_in[5];
    const float* wo     = (const float*)d_in[6];
    float* out = (float*)d_out;

    // QKV projection + RoPE: N total = 4096 + 1024 + 1024 = 6144
    dim3 g1(6144 / 64, MTOT / 64);
    qkv_kernel<<<g1, 256>>>(hidden, wq, wk, wv, cosb, sinb);

    // Flash attention
    size_t smem = (size_t)(128 * 68 + 128 * 68 + 64 * 132 + 64 * 68) * sizeof(float);
    cudaFuncSetAttribute(attn_kernel, cudaFuncAttributeMaxDynamicSharedMemorySize, (int)smem);
    attn_kernel<<<dim3(SEQ / 64, NH, BATCH), 256, smem>>>();

    // Output projection
    dim3 g3(HID / 64, MTOT / 64);
    oproj_kernel<<<g3, 256>>>(wo, out);
}

// round 3
// speedup vs baseline: 2.9153x; 2.9153x over previous
#include <cuda_runtime.h>
#include <cuda_bf16.h>
#include <cstdint>
#include <math.h>

#define BATCH 2
#define SEQ   2048
#define HID   4096
#define NH    32
#define NKV   8
#define HD    128
#define GQA   4
#define MTOT  (BATCH*SEQ)
#define NQK   6144
#define K_DIM 4096
#define NKCH  64
#define TILE_BYTES 16384
#define STAGE_BYTES (4*TILE_BYTES)

#if defined(__CUDA_ARCH__) && defined(__CUDA_ARCH_FEAT_SM103_ALL)
#define USE_TC 1
#else
#define USE_TC 0
#endif

__device__ float g_q[(size_t)BATCH*NH*SEQ*HD];
__device__ float g_k[(size_t)BATCH*NKV*SEQ*HD];
__device__ float g_v[(size_t)BATCH*NKV*SEQ*HD];
__device__ float g_attn[(size_t)BATCH*SEQ*NH*HD];

__device__ __nv_bfloat16 g_xh[(size_t)MTOT*HID],  g_xl[(size_t)MTOT*HID];
__device__ __nv_bfloat16 g_wh[(size_t)NQK*HID],   g_wl[(size_t)NQK*HID];
__device__ __nv_bfloat16 g_woh[(size_t)HID*HID],  g_wol[(size_t)HID*HID];
__device__ __nv_bfloat16 g_ah[(size_t)MTOT*HID],  g_al[(size_t)MTOT*HID];

// ---------------- helpers (generic-target safe) ----------------
__device__ __forceinline__ uint32_t smem_u32(const void* p){
    uint32_t a;
    asm("{ .reg .u64 t; cvta.to.shared.u64 t, %1; cvt.u32.u64 %0, t; }" : "=r"(a) : "l"(p));
    return a;
}
__device__ __forceinline__ uint32_t swz(uint32_t o){ return o ^ ((o >> 3) & 0x70); }
__device__ __forceinline__ void cp16(uint32_t d, const void* s){
    asm volatile("cp.async.cg.shared.global [%0], [%1], 16;" :: "r"(d), "l"(s));
}
__device__ __forceinline__ void cp_commit(){ asm volatile("cp.async.commit_group;" ::: "memory"); }
__device__ __forceinline__ void cp_wait0(){ asm volatile("cp.async.wait_group 0;" ::: "memory"); }

__device__ __forceinline__ void ldm_x4(uint32_t addr, uint32_t r[4]){
    asm volatile("ldmatrix.sync.aligned.m8n8.x4.shared.b16 {%0,%1,%2,%3}, [%4];"
                 : "=r"(r[0]), "=r"(r[1]), "=r"(r[2]), "=r"(r[3]) : "r"(addr));
}
__device__ __forceinline__ void mma_bf16(float c[4], const uint32_t a[4], const uint32_t b[2]){
    asm volatile("mma.sync.aligned.m16n8k16.row.col.f32.bf16.bf16.f32 "
                 "{%0,%1,%2,%3}, {%4,%5,%6,%7}, {%8,%9}, {%0,%1,%2,%3};"
                 : "+f"(c[0]), "+f"(c[1]), "+f"(c[2]), "+f"(c[3])
                 : "r"(a[0]), "r"(a[1]), "r"(a[2]), "r"(a[3]), "r"(b[0]), "r"(b[1]));
}

#if USE_TC
__device__ __forceinline__ uint32_t elect1(){
    uint32_t p;
    asm volatile("{ .reg .pred P; elect.sync _|P, 0xFFFFFFFF; selp.b32 %0,1,0,P; }" : "=r"(p));
    return p;
}
__device__ __forceinline__ void mbar_init(uint32_t a, uint32_t c){
    asm volatile("mbarrier.init.shared.b64 [%0], %1;" :: "r"(a), "r"(c) : "memory");
}
__device__ __forceinline__ void mbar_inval(uint32_t a){
    asm volatile("mbarrier.inval.shared.b64 [%0];" :: "r"(a) : "memory");
}
__device__ __forceinline__ void mbar_wait(uint32_t mb, int parity){
    asm volatile(
        "{\n\t.reg .pred P;\n"
        "W0_%=:\n\t"
        "mbarrier.try_wait.parity.acquire.cta.shared::cta.b64 P, [%0], %1, 0x989680;\n\t"
        "@P bra W1_%=;\n\t"
        "bra W0_%=;\n"
        "W1_%=:\n\t}"
        :: "r"(mb), "r"(parity) : "memory");
}
#define SMEM_DESC_SW128 ((2ULL<<61)|(1ULL<<46)|(64ULL<<32)|(1ULL<<16))
__device__ __forceinline__ uint64_t mk_desc(uint32_t a){
    return SMEM_DESC_SW128 | ((uint64_t)(a >> 4) & 0x3FFF);
}
__device__ __forceinline__ void mma_f16_ss(uint32_t d, uint64_t ad, uint64_t bd,
                                           uint32_t idesc, uint32_t en){
    asm volatile(
        "{\n\t.reg .pred p;\n\t"
        "setp.ne.u32 p, %5, 0;\n\t"
        "tcgen05.mma.cta_group::1.kind::f16 [%0], %1, %2, %3, {%4,%4,%4,%4}, p;\n\t}"
        :: "r"(d), "l"(ad), "l"(bd), "r"(idesc), "r"(0u), "r"(en) : "memory");
}
#define LDTM_X32(r, addr) \
    asm volatile( \
        "tcgen05.ld.sync.aligned.32x32b.x32.b32 " \
        "{%0, %1, %2, %3, %4, %5, %6, %7, " \
        " %8, %9, %10, %11, %12, %13, %14, %15, " \
        " %16, %17, %18, %19, %20, %21, %22, %23, " \
        " %24, %25, %26, %27, %28, %29, %30, %31}, [%32];" \
        : "=r"((r)[0]),  "=r"((r)[1]),  "=r"((r)[2]),  "=r"((r)[3]), \
          "=r"((r)[4]),  "=r"((r)[5]),  "=r"((r)[6]),  "=r"((r)[7]), \
          "=r"((r)[8]),  "=r"((r)[9]),  "=r"((r)[10]), "=r"((r)[11]), \
          "=r"((r)[12]), "=r"((r)[13]), "=r"((r)[14]), "=r"((r)[15]), \
          "=r"((r)[16]), "=r"((r)[17]), "=r"((r)[18]), "=r"((r)[19]), \
          "=r"((r)[20]), "=r"((r)[21]), "=r"((r)[22]), "=r"((r)[23]), \
          "=r"((r)[24]), "=r"((r)[25]), "=r"((r)[26]), "=r"((r)[27]), \
          "=r"((r)[28]), "=r"((r)[29]), "=r"((r)[30]), "=r"((r)[31]) \
        : "r"(addr))
#endif  // USE_TC

// ---------------- fp32 -> bf16 hi/lo split ----------------
__global__ __launch_bounds__(256) void split_kernel(
    const float* __restrict__ src, __nv_bfloat16* __restrict__ hi,
    __nv_bfloat16* __restrict__ lo, int n)
{
    int i = (blockIdx.x * 256 + threadIdx.x) * 4;
    if (i >= n) return;
    float4 v = *reinterpret_cast<const float4*>(src + i);
    float x[4] = {v.x, v.y, v.z, v.w};
    __nv_bfloat16 h[4], l[4];
#pragma unroll
    for (int j = 0; j < 4; j++) {
        h[j] = __float2bfloat16(x[j]);
        l[j] = __float2bfloat16(x[j] - __bfloat162float(h[j]));
    }
    *reinterpret_cast<uint2*>(hi + i) = *reinterpret_cast<uint2*>(h);
    *reinterpret_cast<uint2*>(lo + i) = *reinterpret_cast<uint2*>(l);
}

#if !USE_TC
// mma.sync consume of one 64-K chunk: one product term (A tile x B tile)
__device__ __forceinline__ void consume_chunk_hmma(
    uint32_t abase, uint32_t bbase, int a_row_off, int b_row_off,
    float acc[4][4][4])
{
#pragma unroll
    for (int ks = 0; ks < 4; ks++) {
        uint32_t a[4][4];
#pragma unroll
        for (int mt = 0; mt < 4; mt++)
            ldm_x4(abase + swz(a_row_off + mt * 2048 + ks * 32), a[mt]);
        uint32_t b[2][4];
#pragma unroll
        for (int np = 0; np < 2; np++)
            ldm_x4(bbase + swz(b_row_off + np * 2048 + ks * 32), b[np]);
#pragma unroll
        for (int mt = 0; mt < 4; mt++)
#pragma unroll
            for (int nt = 0; nt < 4; nt++)
                mma_bf16(acc[mt][nt], a[mt], &b[nt >> 1][(nt & 1) * 2]);
    }
}
#endif

// ---------------- bf16x3 GEMM (tcgen05 if available, else mma.sync) --------
// MODE 0: QKV projection + RoPE epilogue -> g_q/g_k/g_v. MODE 1: C=A@B^T -> outp.
template<int MODE>
__global__ __launch_bounds__(256, 1)
void gemm_bf16x3(
    const __nv_bfloat16* __restrict__ Ahp, const __nv_bfloat16* __restrict__ Alp,
    const __nv_bfloat16* __restrict__ Bhp, const __nv_bfloat16* __restrict__ Blp,
    const float* __restrict__ cosb, const float* __restrict__ sinb,
    float* __restrict__ outp)
{
    extern __shared__ char smem_raw[];
    const uint32_t sb = (smem_u32(smem_raw) + 1023) & ~1023u;
    const int tid = threadIdx.x;
    const int wid = tid >> 5, lane = tid & 31;
    const int m0 = blockIdx.y * 128, n0 = blockIdx.x * 128;

    const __nv_bfloat16* a_h = Ahp + (size_t)m0 * K_DIM;
    const __nv_bfloat16* a_l = Alp + (size_t)m0 * K_DIM;
    const __nv_bfloat16* b_h = Bhp + (size_t)n0 * K_DIM;
    const __nv_bfloat16* b_l = Blp + (size_t)n0 * K_DIM;

    auto load_stage = [&](int buf, int kc) {
        uint32_t st = sb + 1024 + buf * STAGE_BYTES;
        int k0 = kc * 64;
#pragma unroll
        for (int t = 0; t < 4; t++) {
            int id = tid + t * 256;
            int rr = id >> 3, cc = id & 7;
            uint32_t off = swz(rr * 128 + cc * 16);
            size_t go = (size_t)rr * K_DIM + k0 + cc * 8;
            cp16(st + off,                a_h + go);
            cp16(st + TILE_BYTES + off,   a_l + go);
            cp16(st + 2*TILE_BYTES + off, b_h + go);
            cp16(st + 3*TILE_BYTES + off, b_l + go);
        }
    };

#if USE_TC
    if (wid == 0)
        asm volatile("tcgen05.alloc.cta_group::1.sync.aligned.shared::cta.b32 [%0], %1;"
                     :: "r"(sb), "r"(128u) : "memory");
    if (tid == 0) { mbar_init(sb + 8, 1); mbar_init(sb + 16, 1); }
    __syncthreads();
    uint32_t tmem;
    asm volatile("ld.shared.b32 %0, [%1];" : "=r"(tmem) : "r"(sb));
    const uint32_t IDESC = 0x8200490u;  // f32 acc, bf16 a/b, M=128, N=128
    int ph0 = 0, ph1 = 0;
#else
    const int warp_m = (wid >> 2) * 64;   // 0 / 64
    const int warp_n = (wid & 3) * 32;    // 0..96
    const int a_row_off = (warp_m + (lane & 15)) * 128 + ((lane >> 4) << 3) * 2;
    const int b_row_off = (warp_n + (lane & 7) + ((lane & 16) >> 1)) * 128 + (lane & 8) * 2;
    float acc[4][4][4];
#pragma unroll
    for (int mt = 0; mt < 4; mt++)
#pragma unroll
        for (int nt = 0; nt < 4; nt++)
#pragma unroll
            for (int e = 0; e < 4; e++) acc[mt][nt][e] = 0.0f;
#endif

    load_stage(0, 0);
    cp_commit();

    for (int kc = 0; kc < NKCH; kc++) {
        int buf = kc & 1;
        uint32_t st = sb + 1024 + buf * STAGE_BYTES;
        cp_wait0();
        asm volatile("fence.proxy.async.shared::cta;" ::: "memory");
        __syncthreads();

#if USE_TC
        if (wid == 0 && elect1()) {
            uint64_t dah = mk_desc(st);
            uint64_t dal = mk_desc(st + TILE_BYTES);
            uint64_t dbh = mk_desc(st + 2*TILE_BYTES);
            uint64_t dbl = mk_desc(st + 3*TILE_BYTES);
#pragma unroll
            for (int ks = 0; ks < 4; ks++) {
                uint32_t en0 = (kc > 0) || (ks > 0);
                mma_f16_ss(tmem, dah + ks*2, dbh + ks*2, IDESC, en0);
                mma_f16_ss(tmem, dal + ks*2, dbh + ks*2, IDESC, 1u);
                mma_f16_ss(tmem, dah + ks*2, dbl + ks*2, IDESC, 1u);
            }
            asm volatile(
                "tcgen05.commit.cta_group::1.mbarrier::arrive::one.shared::cluster.b64 [%0];"
                :: "r"(sb + 8 + buf * 8) : "memory");
        }
        if (kc + 1 < NKCH) {
            if (kc >= 1) {
                int s = 1 - buf;
                if (s == 0) { mbar_wait(sb + 8,  ph0); ph0 ^= 1; }
                else        { mbar_wait(sb + 16, ph1); ph1 ^= 1; }
            }
            load_stage((kc + 1) & 1, kc + 1);
            cp_commit();
        }
#else
        if (kc + 1 < NKCH) { load_stage((kc + 1) & 1, kc + 1); cp_commit(); }
        consume_chunk_hmma(st,              st + 2*TILE_BYTES, a_row_off, b_row_off, acc);
        consume_chunk_hmma(st + TILE_BYTES, st + 2*TILE_BYTES, a_row_off, b_row_off, acc);
        consume_chunk_hmma(st,              st + 3*TILE_BYTES, a_row_off, b_row_off, acc);
#endif
    }

#if USE_TC
    { int s = (NKCH - 1) & 1;
      if (s == 0) mbar_wait(sb + 8, ph0); else mbar_wait(sb + 16, ph1); }
    asm volatile("tcgen05.fence::after_thread_sync;" ::: "memory");

    const int sub = wid & 3, half = wid >> 2;
    const int m = m0 + sub * 32 + lane;
#pragma unroll
    for (int chnk = 0; chnk < 2; chnk++) {
        const int cb = half * 64 + chnk * 32;
        uint32_t regs[32];
        LDTM_X32(regs, tmem + cb);
        asm volatile("tcgen05.wait::ld.sync.aligned;" ::: "memory");

        if (MODE == 0) {
            const int b = m >> 11, s = m & 2047;
            float o[32];
            if (n0 < 5120) {
#pragma unroll
                for (int j = 0; j < 32; j += 2) {
                    float x0 = __uint_as_float(regs[j]);
                    float x1 = __uint_as_float(regs[j + 1]);
                    int d = cb + j;
                    float c  = __ldg(cosb + s * HD + d);
                    float sn = __ldg(sinb + s * HD + d);
                    o[j]     = x0 * c - x1 * sn;
                    o[j + 1] = x1 * c + x0 * sn;
                }
            } else {
#pragma unroll
                for (int j = 0; j < 32; j++) o[j] = __uint_as_float(regs[j]);
            }
            float* dst;
            if (n0 < 4096) {
                int h = n0 >> 7;
                dst = g_q + (((size_t)b * NH + h) * SEQ + s) * HD + cb;
            } else if (n0 < 5120) {
                int h = (n0 - 4096) >> 7;
                dst = g_k + (((size_t)b * NKV + h) * SEQ + s) * HD + cb;
            } else {
                int h = (n0 - 5120) >> 7;
                dst = g_v + (((size_t)b * NKV + h) * SEQ + s) * HD + cb;
            }
#pragma unroll
            for (int j = 0; j < 32; j += 4)
                *reinterpret_cast<float4*>(dst + j) =
                    make_float4(o[j], o[j+1], o[j+2], o[j+3]);
        } else {
            float* dst = outp + (size_t)m * HID + n0 + cb;
#pragma unroll
            for (int j = 0; j < 32; j += 4)
                *reinterpret_cast<float4*>(dst + j) =
                    make_float4(__uint_as_float(regs[j]),   __uint_as_float(regs[j+1]),
                                __uint_as_float(regs[j+2]), __uint_as_float(regs[j+3]));
        }
    }
    __syncthreads();
    if (tid == 0) { mbar_inval(sb + 8); mbar_inval(sb + 16); }
    if (wid == 0) {
        asm volatile("tcgen05.relinquish_alloc_permit.cta_group::1.sync.aligned;");
        asm volatile("tcgen05.dealloc.cta_group::1.sync.aligned.b32 %0, %1;"
                     :: "r"(tmem), "r"(128u));
    }
#else
    // mma.sync epilogue: fragments c0,c1 row g; c2,c3 row g+8; cols 2*tg,+1
    const int g = lane >> 2, tg = lane & 3;
#pragma unroll
    for (int mt = 0; mt < 4; mt++) {
#pragma unroll
        for (int nt = 0; nt < 4; nt++) {
            int ct = warp_n + nt * 8 + tg * 2;
#pragma unroll
            for (int half = 0; half < 2; half++) {
                int r = warp_m + mt * 16 + g + half * 8;
                float c0 = acc[mt][nt][half * 2];
                float c1 = acc[mt][nt][half * 2 + 1];
                int m = m0 + r;
                if (MODE == 0) {
                    int b = m >> 11, s = m & 2047;
                    if (n0 < 5120) {
                        float c  = __ldg(cosb + s * HD + ct);
                        float sn = __ldg(sinb + s * HD + ct);
                        float o0 = c0 * c - c1 * sn;
                        float o1 = c1 * c + c0 * sn;
                        c0 = o0; c1 = o1;
                    }
                    float* dst;
                    if (n0 < 4096) {
                        int h = n0 >> 7;
                        dst = g_q + (((size_t)b * NH + h) * SEQ + s) * HD + ct;
                    } else if (n0 < 5120) {
                        int h = (n0 - 4096) >> 7;
                        dst = g_k + (((size_t)b * NKV + h) * SEQ + s) * HD + ct;
                    } else {
                        int h = (n0 - 5120) >> 7;
                        dst = g_v + (((size_t)b * NKV + h) * SEQ + s) * HD + ct;
                    }
                    *reinterpret_cast<float2*>(dst) = make_float2(c0, c1);
                } else {
                    *reinterpret_cast<float2*>(outp + (size_t)m * HID + n0 + ct) =
                        make_float2(c0, c1);
                }
            }
        }
    }
#endif
}

// ---------------- fp32 causal flash attention (unchanged) ----------------
__device__ __forceinline__ void load_tile_T(const float* __restrict__ gsrc,
                                            float* __restrict__ dst,
                                            int row0, float mul, int tid)
{
    int lane = tid & 31;
    int warp = tid >> 5;
#pragma unroll
    for (int t = 0; t < 8; t++) {
        int unit = warp + t * 8;
        int rg   = unit & 15;
        int cg   = unit >> 4;
        int c    = cg * 32 + lane;
        const float* gp = gsrc + (size_t)(row0 + rg * 4) * HD + c;
        float v0 = gp[0]    * mul;
        float v1 = gp[HD]   * mul;
        float v2 = gp[2*HD] * mul;
        float v3 = gp[3*HD] * mul;
        *reinterpret_cast<float4*>(dst + c * 68 + rg * 4) = make_float4(v0, v1, v2, v3);
    }
}

__global__ __launch_bounds__(256) void attn_kernel()
{
    extern __shared__ float sm[];
    float* Qs = sm;
    float* Ks = Qs + 128 * 68;
    float* Vs = Ks + 128 * 68;
    float* Ps = Vs + 64 * 132;

    const int tid = threadIdx.x;
    const int tx = tid & 15;
    const int ty = tid >> 4;
    const int q0 = blockIdx.x * 64;
    const int h  = blockIdx.y;
    const int b  = blockIdx.z;
    const int kvh = h / GQA;

    const float scale = 0.08838834764831845f;
    const float* qptr = g_q + (((size_t)b * NH  + h)   * SEQ) * HD;
    const float* kptr = g_k + (((size_t)b * NKV + kvh) * SEQ) * HD;
    const float* vptr = g_v + (((size_t)b * NKV + kvh) * SEQ) * HD;

    load_tile_T(qptr, Qs, q0, scale, tid);

    float acc[4][8];
#pragma unroll
    for (int i = 0; i < 4; i++)
#pragma unroll
        for (int j = 0; j < 8; j++) acc[i][j] = 0.0f;
    float mi[4], li[4];
#pragma unroll
    for (int i = 0; i < 4; i++) { mi[i] = -1e30f; li[i] = 0.0f; }

    const int nkb = q0 / 64 + 1;
    for (int kb = 0; kb < nkb; kb++) {
        const int k0 = kb * 64;
        load_tile_T(kptr, Ks, k0, 1.0f, tid);
#pragma unroll
        for (int t = 0; t < 8; t++) {
            int id = tid + t * 256;
            int r  = id >> 5;
            int c4 = (id & 31) << 2;
            float4 vv = *reinterpret_cast<const float4*>(&vptr[(size_t)(k0 + r) * HD + c4]);
            *reinterpret_cast<float4*>(&Vs[r * 132 + c4]) = vv;
        }
        __syncthreads();

        float sc[4][4];
#pragma unroll
        for (int i = 0; i < 4; i++)
#pragma unroll
            for (int j = 0; j < 4; j++) sc[i][j] = 0.0f;

#pragma unroll 8
        for (int d = 0; d < 128; d++) {
            float4 a4 = *reinterpret_cast<const float4*>(&Qs[d * 68 + ty * 4]);
            float4 b4 = *reinterpret_cast<const float4*>(&Ks[d * 68 + tx * 4]);
            float a[4] = {a4.x, a4.y, a4.z, a4.w};
            float bb[4] = {b4.x, b4.y, b4.z, b4.w};
#pragma unroll
            for (int i = 0; i < 4; i++)
#pragma unroll
                for (int j = 0; j < 4; j++) sc[i][j] = fmaf(a[i], bb[j], sc[i][j]);
        }

        const bool diag = (kb == nkb - 1);
#pragma unroll
        for (int i = 0; i < 4; i++) {
            int qi = q0 + ty * 4 + i;
            float rm = -1e30f;
#pragma unroll
            for (int j = 0; j < 4; j++) {
                if (diag) {
                    int kj = k0 + tx * 4 + j;
                    if (kj > qi) sc[i][j] = -1e30f;
                }
                rm = fmaxf(rm, sc[i][j]);
            }
#pragma unroll
            for (int off = 8; off >= 1; off >>= 1)
                rm = fmaxf(rm, __shfl_xor_sync(0xffffffffu, rm, off));
            float nm = fmaxf(mi[i], rm);
            float f  = __expf(mi[i] - nm);
            float rs = 0.0f;
#pragma unroll
            for (int j = 0; j < 4; j++) {
                float p = __expf(sc[i][j] - nm);
                sc[i][j] = p;
                rs += p;
            }
#pragma unroll
            for (int off = 8; off >= 1; off >>= 1)
                rs += __shfl_xor_sync(0xffffffffu, rs, off);
            li[i] = li[i] * f + rs;
            mi[i] = nm;
#pragma unroll
            for (int j = 0; j < 8; j++) acc[i][j] *= f;
            *reinterpret_cast<float4*>(&Ps[(ty * 4 + i) * 68 + tx * 4]) =
                make_float4(sc[i][0], sc[i][1], sc[i][2], sc[i][3]);
        }
        __syncthreads();

#pragma unroll 4
        for (int kk = 0; kk < 64; kk++) {
            float p[4];
#pragma unroll
            for (int i = 0; i < 4; i++) p[i] = Ps[(ty * 4 + i) * 68 + kk];
            float4 v0 = *reinterpret_cast<const float4*>(&Vs[kk * 132 + tx * 8]);
            float4 v1 = *reinterpret_cast<const float4*>(&Vs[kk * 132 + tx * 8 + 4]);
            float v[8] = {v0.x, v0.y, v0.z, v0.w, v1.x, v1.y, v1.z, v1.w};
#pragma unroll
            for (int i = 0; i < 4; i++)
#pragma unroll
                for (int j = 0; j < 8; j++) acc[i][j] = fmaf(p[i], v[j], acc[i][j]);
        }
        __syncthreads();
    }

#pragma unroll
    for (int i = 0; i < 4; i++) {
        int qi = q0 + ty * 4 + i;
        float inv = 1.0f / li[i];
        float* op = g_attn + ((size_t)b * SEQ + qi) * (NH * HD) + h * HD + tx * 8;
        *reinterpret_cast<float4*>(op) =
            make_float4(acc[i][0]*inv, acc[i][1]*inv, acc[i][2]*inv, acc[i][3]*inv);
        *reinterpret_cast<float4*>(op + 4) =
            make_float4(acc[i][4]*inv, acc[i][5]*inv, acc[i][6]*inv, acc[i][7]*inv);
    }
}

extern "C" void kernel_launch(void* const* d_in, const int* in_sizes, int n_in,
                              void* d_out, int out_size)
{
    const float* hidden = (const float*)d_in[0];
    const float* cosb   = (const float*)d_in[1];
    const float* sinb   = (const float*)d_in[2];
    const float* wq     = (const float*)d_in[3];
    const float* wk     = (const float*)d_in[4];
    const float* wv     = (const float*)d_in[5];
    const float* wo     = (const float*)d_in[6];
    float* out = (float*)d_out;

    __nv_bfloat16 *xh, *xl, *wh, *wl, *woh, *wol, *ah, *al;
    float* attn_ptr;
    cudaGetSymbolAddress((void**)&xh,  g_xh);  cudaGetSymbolAddress((void**)&xl,  g_xl);
    cudaGetSymbolAddress((void**)&wh,  g_wh);  cudaGetSymbolAddress((void**)&wl,  g_wl);
    cudaGetSymbolAddress((void**)&woh, g_woh); cudaGetSymbolAddress((void**)&wol, g_wol);
    cudaGetSymbolAddress((void**)&ah,  g_ah);  cudaGetSymbolAddress((void**)&al,  g_al);
    cudaGetSymbolAddress((void**)&attn_ptr, g_attn);

    auto blocks = [](size_t n){ return (unsigned)((n / 4 + 255) / 256); };

    split_kernel<<<blocks((size_t)MTOT*HID), 256>>>(hidden, xh, xl, MTOT*HID);
    split_kernel<<<blocks((size_t)4096*4096), 256>>>(wq, wh, wl, 4096*4096);
    split_kernel<<<blocks((size_t)1024*4096), 256>>>(wk, wh + (size_t)4096*4096,
                                                     wl + (size_t)4096*4096, 1024*4096);
    split_kernel<<<blocks((size_t)1024*4096), 256>>>(wv, wh + (size_t)5120*4096,
                                                     wl + (size_t)5120*4096, 1024*4096);
    split_kernel<<<blocks((size_t)HID*HID), 256>>>(wo, woh, wol, HID*HID);

    const int gemm_smem = 2048 + 2 * STAGE_BYTES;
    cudaFuncSetAttribute(gemm_bf16x3<0>, cudaFuncAttributeMaxDynamicSharedMemorySize, gemm_smem);
    cudaFuncSetAttribute(gemm_bf16x3<1>, cudaFuncAttributeMaxDynamicSharedMemorySize, gemm_smem);

    gemm_bf16x3<0><<<dim3(48, 32), 256, gemm_smem>>>(xh, xl, wh, wl, cosb, sinb, nullptr);

    size_t smem = (size_t)(128*68 + 128*68 + 64*132 + 64*68) * sizeof(float);
    cudaFuncSetAttribute(attn_kernel, cudaFuncAttributeMaxDynamicSharedMemorySize, (int)smem);
    attn_kernel<<<dim3(SEQ/64, NH, BATCH), 256, smem>>>();

    split_kernel<<<blocks((size_t)MTOT*HID), 256>>>(attn_ptr, ah, al, MTOT*HID);
    gemm_bf16x3<1><<<dim3(32, 32), 256, gemm_smem>>>(ah, al, woh, wol, nullptr, nullptr, out);
}

// round 6
// speedup vs baseline: 3.8135x; 1.3081x over previous
#include <cuda_runtime.h>
#include <cuda_bf16.h>
#include <cstdint>
#include <math.h>

#define BATCH 2
#define SEQ   2048
#define HID   4096
#define NH    32
#define NKV   8
#define HD    128
#define GQA   4
#define MTOT  (BATCH*SEQ)
#define NQK   6144
#define K_DIM 4096
#define NKCH  64
#define TILE_BYTES 16384
#define STAGE_BYTES (4*TILE_BYTES)

// attention tile constants (padded rows: 128 bf16 + 8 pad = 272 bytes)
#define ROWB   272
#define QTILE  (128*ROWB)          // 34816
#define KTILE  (64*ROWB)           // 17408
#define KVBUF  (4*KTILE)           // 69632
#define ATTN_SMEM (2*QTILE + 2*KVBUF)  // 208896

// q pre-scale: 1/sqrt(128) * log2(e)
#define QSC (0.08838834764831845f * 1.44269504088896340736f)

// ---------------- scratch ----------------
__device__ __nv_bfloat16 g_qh[(size_t)BATCH*NH*SEQ*HD],  g_ql[(size_t)BATCH*NH*SEQ*HD];
__device__ __nv_bfloat16 g_kh[(size_t)BATCH*NKV*SEQ*HD], g_kl[(size_t)BATCH*NKV*SEQ*HD];
__device__ __nv_bfloat16 g_vh[(size_t)BATCH*NKV*SEQ*HD], g_vl[(size_t)BATCH*NKV*SEQ*HD];

__device__ __nv_bfloat16 g_xh[(size_t)MTOT*HID],  g_xl[(size_t)MTOT*HID];
__device__ __nv_bfloat16 g_wh[(size_t)NQK*HID],   g_wl[(size_t)NQK*HID];
__device__ __nv_bfloat16 g_woh[(size_t)HID*HID],  g_wol[(size_t)HID*HID];
__device__ __nv_bfloat16 g_ah[(size_t)MTOT*HID],  g_al[(size_t)MTOT*HID];

// ---------------- helpers ----------------
__device__ __forceinline__ uint32_t smem_u32(const void* p){
    uint32_t a;
    asm("{ .reg .u64 t; cvta.to.shared.u64 t, %1; cvt.u32.u64 %0, t; }" : "=r"(a) : "l"(p));
    return a;
}
__device__ __forceinline__ uint32_t swz(uint32_t o){ return o ^ ((o >> 3) & 0x70); }
__device__ __forceinline__ void cp16(uint32_t d, const void* s){
    asm volatile("cp.async.cg.shared.global [%0], [%1], 16;" :: "r"(d), "l"(s));
}
__device__ __forceinline__ void cp_commit(){ asm volatile("cp.async.commit_group;" ::: "memory"); }
__device__ __forceinline__ void cp_wait0(){ asm volatile("cp.async.wait_group 0;" ::: "memory"); }

__device__ __forceinline__ void ldm_x4(uint32_t addr, uint32_t r[4]){
    asm volatile("ldmatrix.sync.aligned.m8n8.x4.shared.b16 {%0,%1,%2,%3}, [%4];"
                 : "=r"(r[0]), "=r"(r[1]), "=r"(r[2]), "=r"(r[3]) : "r"(addr));
}
__device__ __forceinline__ void ldm_x4_t(uint32_t addr, uint32_t r[4]){
    asm volatile("ldmatrix.sync.aligned.m8n8.x4.trans.shared.b16 {%0,%1,%2,%3}, [%4];"
                 : "=r"(r[0]), "=r"(r[1]), "=r"(r[2]), "=r"(r[3]) : "r"(addr));
}
__device__ __forceinline__ void mma_bf16(float c[4], const uint32_t a[4], const uint32_t b[2]){
    asm volatile("mma.sync.aligned.m16n8k16.row.col.f32.bf16.bf16.f32 "
                 "{%0,%1,%2,%3}, {%4,%5,%6,%7}, {%8,%9}, {%0,%1,%2,%3};"
                 : "+f"(c[0]), "+f"(c[1]), "+f"(c[2]), "+f"(c[3])
                 : "r"(a[0]), "r"(a[1]), "r"(a[2]), "r"(a[3]), "r"(b[0]), "r"(b[1]));
}
__device__ __forceinline__ float ex2f(float x){
    float y; asm("ex2.approx.ftz.f32 %0, %1;" : "=f"(y) : "f"(x)); return y;
}
// pack two floats into bf16x2 hi, and their residuals into bf16x2 lo
__device__ __forceinline__ uint32_t splitpack(float v0, float v1, uint32_t& lo){
    uint32_t hi;
    asm("cvt.rn.bf16x2.f32 %0, %1, %2;" : "=r"(hi) : "f"(v1), "f"(v0));
    float h0 = __uint_as_float(hi << 16);
    float h1 = __uint_as_float(hi & 0xffff0000u);
    asm("cvt.rn.bf16x2.f32 %0, %1, %2;" : "=r"(lo) : "f"(v1 - h1), "f"(v0 - h0));
    return hi;
}

// ---------------- fp32 -> bf16 hi/lo split ----------------
__global__ __launch_bounds__(256) void split_kernel(
    const float* __restrict__ src, __nv_bfloat16* __restrict__ hi,
    __nv_bfloat16* __restrict__ lo, int n)
{
    int i = (blockIdx.x * 256 + threadIdx.x) * 4;
    if (i >= n) return;
    float4 v = *reinterpret_cast<const float4*>(src + i);
    float x[4] = {v.x, v.y, v.z, v.w};
    __nv_bfloat16 h[4], l[4];
#pragma unroll
    for (int j = 0; j < 4; j++) {
        h[j] = __float2bfloat16(x[j]);
        l[j] = __float2bfloat16(x[j] - __bfloat162float(h[j]));
    }
    *reinterpret_cast<uint2*>(hi + i) = *reinterpret_cast<uint2*>(h);
    *reinterpret_cast<uint2*>(lo + i) = *reinterpret_cast<uint2*>(l);
}

// ---------------- mma.sync chunk consume for projection GEMMs ----------------
__device__ __forceinline__ void consume_chunk_hmma(
    uint32_t abase, uint32_t bbase, int a_row_off, int b_row_off,
    float acc[4][4][4])
{
#pragma unroll
    for (int ks = 0; ks < 4; ks++) {
        uint32_t a[4][4];
#pragma unroll
        for (int mt = 0; mt < 4; mt++)
            ldm_x4(abase + swz(a_row_off + mt * 2048 + ks * 32), a[mt]);
        uint32_t b[2][4];
#pragma unroll
        for (int np = 0; np < 2; np++)
            ldm_x4(bbase + swz(b_row_off + np * 2048 + ks * 32), b[np]);
#pragma unroll
        for (int mt = 0; mt < 4; mt++)
#pragma unroll
            for (int nt = 0; nt < 4; nt++)
                mma_bf16(acc[mt][nt], a[mt], &b[nt >> 1][(nt & 1) * 2]);
    }
}

// ---------------- bf16x3 GEMM ----------------
// MODE 0: QKV projection + RoPE, writes bf16 hi/lo q/k/v (q pre-scaled by QSC).
// MODE 1: C = A @ B^T -> fp32 outp.
template<int MODE>
__global__ __launch_bounds__(256, 1)
void gemm_bf16x3(
    const __nv_bfloat16* __restrict__ Ahp, const __nv_bfloat16* __restrict__ Alp,
    const __nv_bfloat16* __restrict__ Bhp, const __nv_bfloat16* __restrict__ Blp,
    const float* __restrict__ cosb, const float* __restrict__ sinb,
    float* __restrict__ outp)
{
    extern __shared__ char smem_raw[];
    const uint32_t sb = (smem_u32(smem_raw) + 1023) & ~1023u;
    const int tid = threadIdx.x;
    const int wid = tid >> 5, lane = tid & 31;
    const int m0 = blockIdx.y * 128, n0 = blockIdx.x * 128;

    const __nv_bfloat16* a_h = Ahp + (size_t)m0 * K_DIM;
    const __nv_bfloat16* a_l = Alp + (size_t)m0 * K_DIM;
    const __nv_bfloat16* b_h = Bhp + (size_t)n0 * K_DIM;
    const __nv_bfloat16* b_l = Blp + (size_t)n0 * K_DIM;

    auto load_stage = [&](int buf, int kc) {
        uint32_t st = sb + buf * STAGE_BYTES;
        int k0 = kc * 64;
#pragma unroll
        for (int t = 0; t < 4; t++) {
            int id = tid + t * 256;
            int rr = id >> 3, cc = id & 7;
            uint32_t off = swz(rr * 128 + cc * 16);
            size_t go = (size_t)rr * K_DIM + k0 + cc * 8;
            cp16(st + off,                a_h + go);
            cp16(st + TILE_BYTES + off,   a_l + go);
            cp16(st + 2*TILE_BYTES + off, b_h + go);
            cp16(st + 3*TILE_BYTES + off, b_l + go);
        }
    };

    const int warp_m = (wid >> 2) * 64;
    const int warp_n = (wid & 3) * 32;
    const int a_row_off = (warp_m + (lane & 15)) * 128 + ((lane >> 4) << 3) * 2;
    const int b_row_off = (warp_n + (lane & 7) + ((lane & 16) >> 1)) * 128 + (lane & 8) * 2;
    float acc[4][4][4];
#pragma unroll
    for (int mt = 0; mt < 4; mt++)
#pragma unroll
        for (int nt = 0; nt < 4; nt++)
#pragma unroll
            for (int e = 0; e < 4; e++) acc[mt][nt][e] = 0.0f;

    load_stage(0, 0);
    cp_commit();

    for (int kc = 0; kc < NKCH; kc++) {
        int buf = kc & 1;
        uint32_t st = sb + buf * STAGE_BYTES;
        cp_wait0();
        __syncthreads();
        if (kc + 1 < NKCH) { load_stage((kc + 1) & 1, kc + 1); cp_commit(); }
        consume_chunk_hmma(st,              st + 2*TILE_BYTES, a_row_off, b_row_off, acc);
        consume_chunk_hmma(st + TILE_BYTES, st + 2*TILE_BYTES, a_row_off, b_row_off, acc);
        consume_chunk_hmma(st,              st + 3*TILE_BYTES, a_row_off, b_row_off, acc);
        __syncthreads();
    }

    const int g2 = lane >> 2, tg = lane & 3;
#pragma unroll
    for (int mt = 0; mt < 4; mt++) {
#pragma unroll
        for (int nt = 0; nt < 4; nt++) {
            int ct = warp_n + nt * 8 + tg * 2;
#pragma unroll
            for (int half = 0; half < 2; half++) {
                int r = warp_m + mt * 16 + g2 + half * 8;
                float c0 = acc[mt][nt][half * 2];
                float c1 = acc[mt][nt][half * 2 + 1];
                int m = m0 + r;
                if (MODE == 0) {
                    int bb = m >> 11, s = m & 2047;
                    int ng = n0 + ct;
                    __nv_bfloat16 *dh, *dl;
                    size_t idx;
                    if (ng < 4096) {
                        int hh = ng >> 7, d = ng & 127;
                        float c  = __ldg(cosb + s * HD + d);
                        float sn = __ldg(sinb + s * HD + d);
                        float o0 = c0 * c - c1 * sn;
                        float o1 = c1 * c + c0 * sn;
                        c0 = o0 * QSC; c1 = o1 * QSC;
                        idx = (((size_t)bb * NH + hh) * SEQ + s) * HD + d;
                        dh = g_qh; dl = g_ql;
                    } else if (ng < 5120) {
                        int hh = (ng - 4096) >> 7, d = ng & 127;
                        float c  = __ldg(cosb + s * HD + d);
                        float sn = __ldg(sinb + s * HD + d);
                        float o0 = c0 * c - c1 * sn;
                        float o1 = c1 * c + c0 * sn;
                        c0 = o0; c1 = o1;
                        idx = (((size_t)bb * NKV + hh) * SEQ + s) * HD + d;
                        dh = g_kh; dl = g_kl;
                    } else {
                        int hh = (ng - 5120) >> 7, d = ng & 127;
                        idx = (((size_t)bb * NKV + hh) * SEQ + s) * HD + d;
                        dh = g_vh; dl = g_vl;
                    }
                    uint32_t lo, hi = splitpack(c0, c1, lo);
                    *reinterpret_cast<uint32_t*>(dh + idx) = hi;
                    *reinterpret_cast<uint32_t*>(dl + idx) = lo;
                } else {
                    *reinterpret_cast<float2*>(outp + (size_t)m * HID + n0 + ct) =
                        make_float2(c0, c1);
                }
            }
        }
    }
}

// ---------------- mma.sync bf16 flash attention ----------------
// BQ=128, BKV=64, 8 warps (each: 16 rows x full width). 3-term hi/lo everywhere.
__global__ __launch_bounds__(256, 1) void attn_mma_kernel()
{
    extern __shared__ char smem_raw[];
    const uint32_t SQH = smem_u32(smem_raw);
    const uint32_t SQL = SQH + QTILE;
    const uint32_t SKV = SQL + QTILE;   // 2 buffers of KVBUF: [KH, KL, VH, VL]

    const int tid = threadIdx.x, wid = tid >> 5, lane = tid & 31;
    const int g = lane >> 2, tg = lane & 3;
    const int q0 = blockIdx.x * 128;
    const int h  = blockIdx.y;
    const int b  = blockIdx.z;
    const int kvh = h >> 2;

    const char* qh = (const char*)(g_qh + (((size_t)b * NH  + h)   * SEQ + q0) * HD);
    const char* ql = (const char*)(g_ql + (((size_t)b * NH  + h)   * SEQ + q0) * HD);
    const char* kh = (const char*)(g_kh + (((size_t)b * NKV + kvh) * SEQ) * HD);
    const char* kl = (const char*)(g_kl + (((size_t)b * NKV + kvh) * SEQ) * HD);
    const char* vh = (const char*)(g_vh + (((size_t)b * NKV + kvh) * SEQ) * HD);
    const char* vl = (const char*)(g_vl + (((size_t)b * NKV + kvh) * SEQ) * HD);

    // FIX (R4 NaN): rows are 256 bytes = 16 chunks of 16B. KV tile: 64 rows x 16
    // chunks = 1024 ids (4 x 256). Q tile: 128 rows x 16 chunks = 2048 ids (8 x 256).
    auto load_kv = [&](int buf, int k0) {
        uint32_t base = SKV + buf * KVBUF;
#pragma unroll
        for (int t = 0; t < 4; t++) {
            int id = tid + t * 256;          // 0..1023
            int r  = id >> 4, c = id & 15;
            size_t go = (size_t)(k0 + r) * 256 + c * 16;
            uint32_t so = r * ROWB + c * 16;
            cp16(base + so,             kh + go);
            cp16(base + KTILE + so,     kl + go);
            cp16(base + 2*KTILE + so,   vh + go);
            cp16(base + 3*KTILE + so,   vl + go);
        }
    };

    // load Q (both tiles) + first K/V block
#pragma unroll
    for (int t = 0; t < 8; t++) {
        int id = tid + t * 256;              // 0..2047
        int r  = id >> 4, c = id & 15;
        size_t go = (size_t)r * 256 + c * 16;
        uint32_t so = r * ROWB + c * 16;
        cp16(SQH + so, qh + go);
        cp16(SQL + so, ql + go);
    }
    load_kv(0, 0);
    cp_commit();

    float o[16][4];
#pragma unroll
    for (int nt = 0; nt < 16; nt++)
#pragma unroll
        for (int e = 0; e < 4; e++) o[nt][e] = 0.0f;
    float m0r = -1e30f, m1r = -1e30f, l0 = 0.0f, l1 = 0.0f;

    const int qi0 = q0 + wid * 16 + g;
    const int nblk = q0 / 64 + 2;

    for (int kb = 0; kb < nblk; kb++) {
        const int k0 = kb * 64;
        cp_wait0();
        __syncthreads();
        const uint32_t KB = SKV + (kb & 1) * KVBUF;
        if (kb + 1 < nblk) { load_kv((kb + 1) & 1, (kb + 1) * 64); cp_commit(); }

        // ---- scores: 3-term QK^T ----
        float sc[8][4];
#pragma unroll
        for (int nt = 0; nt < 8; nt++)
#pragma unroll
            for (int e = 0; e < 4; e++) sc[nt][e] = 0.0f;

#pragma unroll
        for (int ks = 0; ks < 8; ks++) {
            uint32_t aqh[4], aql[4];
            uint32_t qrow = SQH + (wid * 16 + (lane & 15)) * ROWB + ((lane >> 4) << 4) + ks * 32;
            ldm_x4(qrow, aqh);
            ldm_x4(qrow + QTILE, aql);
#pragma unroll
            for (int np = 0; np < 4; np++) {
                uint32_t kaddr = KB + (np * 16 + (lane & 7) + ((lane & 16) >> 1)) * ROWB
                               + ((lane & 8) << 1) + ks * 32;
                uint32_t bh[4], bl[4];
                ldm_x4(kaddr, bh);
                ldm_x4(kaddr + KTILE, bl);
                mma_bf16(sc[2*np],   aqh, bh);     mma_bf16(sc[2*np],   aql, bh);
                mma_bf16(sc[2*np],   aqh, bl);
                mma_bf16(sc[2*np+1], aqh, bh + 2); mma_bf16(sc[2*np+1], aql, bh + 2);
                mma_bf16(sc[2*np+1], aqh, bl + 2);
            }
        }

        // ---- causal mask (only near the diagonal) ----
        if (k0 + 63 > q0) {
#pragma unroll
            for (int nt = 0; nt < 8; nt++) {
                int kc = k0 + nt * 8 + tg * 2;
                if (kc     > qi0)     sc[nt][0] = -1e30f;
                if (kc + 1 > qi0)     sc[nt][1] = -1e30f;
                if (kc     > qi0 + 8) sc[nt][2] = -1e30f;
                if (kc + 1 > qi0 + 8) sc[nt][3] = -1e30f;
            }
        }

        // ---- online softmax (base-2; scale folded into q) ----
        float mx0 = -1e30f, mx1 = -1e30f;
#pragma unroll
        for (int nt = 0; nt < 8; nt++) {
            mx0 = fmaxf(mx0, fmaxf(sc[nt][0], sc[nt][1]));
            mx1 = fmaxf(mx1, fmaxf(sc[nt][2], sc[nt][3]));
        }
        mx0 = fmaxf(mx0, __shfl_xor_sync(0xffffffffu, mx0, 1));
        mx0 = fmaxf(mx0, __shfl_xor_sync(0xffffffffu, mx0, 2));
        mx1 = fmaxf(mx1, __shfl_xor_sync(0xffffffffu, mx1, 1));
        mx1 = fmaxf(mx1, __shfl_xor_sync(0xffffffffu, mx1, 2));
        float nm0 = fmaxf(m0r, mx0), nm1 = fmaxf(m1r, mx1);
        float a0 = ex2f(m0r - nm0),  a1 = ex2f(m1r - nm1);
        m0r = nm0; m1r = nm1;
        l0 *= a0; l1 *= a1;
#pragma unroll
        for (int nt = 0; nt < 16; nt++) {
            o[nt][0] *= a0; o[nt][1] *= a0; o[nt][2] *= a1; o[nt][3] *= a1;
        }
#pragma unroll
        for (int nt = 0; nt < 8; nt++) {
            float p0 = ex2f(sc[nt][0] - nm0);
            float p1 = ex2f(sc[nt][1] - nm0);
            float p2 = ex2f(sc[nt][2] - nm1);
            float p3 = ex2f(sc[nt][3] - nm1);
            sc[nt][0] = p0; sc[nt][1] = p1; sc[nt][2] = p2; sc[nt][3] = p3;
            l0 += p0 + p1; l1 += p2 + p3;
        }

        // ---- PV: 3-term, P fragments built in-register ----
#pragma unroll
        for (int j = 0; j < 4; j++) {
            uint32_t aH[4], aL[4];
            aH[0] = splitpack(sc[2*j][0],   sc[2*j][1],   aL[0]);
            aH[1] = splitpack(sc[2*j][2],   sc[2*j][3],   aL[1]);
            aH[2] = splitpack(sc[2*j+1][0], sc[2*j+1][1], aL[2]);
            aH[3] = splitpack(sc[2*j+1][2], sc[2*j+1][3], aL[3]);
#pragma unroll
            for (int nb = 0; nb < 8; nb++) {
                uint32_t vaddr = KB + 2*KTILE + (j * 16 + (lane & 15)) * ROWB
                               + ((nb * 16 + ((lane >> 4) << 3)) << 1);
                uint32_t vhf[4], vlf[4];
                ldm_x4_t(vaddr, vhf);
                ldm_x4_t(vaddr + KTILE, vlf);
                mma_bf16(o[2*nb],   aH, vhf);     mma_bf16(o[2*nb],   aL, vhf);
                mma_bf16(o[2*nb],   aH, vlf);
                mma_bf16(o[2*nb+1], aH, vhf + 2); mma_bf16(o[2*nb+1], aL, vhf + 2);
                mma_bf16(o[2*nb+1], aH, vlf + 2);
            }
        }
    }

    // ---- finalize: reduce l over quad, divide, write bf16 hi/lo ----
    l0 += __shfl_xor_sync(0xffffffffu, l0, 1);
    l0 += __shfl_xor_sync(0xffffffffu, l0, 2);
    l1 += __shfl_xor_sync(0xffffffffu, l1, 1);
    l1 += __shfl_xor_sync(0xffffffffu, l1, 2);
    float inv0 = 1.0f / l0, inv1 = 1.0f / l1;

    size_t row0 = ((size_t)b * SEQ + qi0)     * HID + h * 128;
    size_t row1 = ((size_t)b * SEQ + qi0 + 8) * HID + h * 128;
#pragma unroll
    for (int nt = 0; nt < 16; nt++) {
        int ct = nt * 8 + tg * 2;
        uint32_t lo, hi;
        hi = splitpack(o[nt][0] * inv0, o[nt][1] * inv0, lo);
        *reinterpret_cast<uint32_t*>(g_ah + row0 + ct) = hi;
        *reinterpret_cast<uint32_t*>(g_al + row0 + ct) = lo;
        hi = splitpack(o[nt][2] * inv1, o[nt][3] * inv1, lo);
        *reinterpret_cast<uint32_t*>(g_ah + row1 + ct) = hi;
        *reinterpret_cast<uint32_t*>(g_al + row1 + ct) = lo;
    }
}

// ---------------------------------------------------------------------------
extern "C" void kernel_launch(void* const* d_in, const int* in_sizes, int n_in,
                              void* d_out, int out_size)
{
    const float* hidden = (const float*)d_in[0];
    const float* cosb   = (const float*)d_in[1];
    const float* sinb   = (const float*)d_in[2];
    const float* wq     = (const float*)d_in[3];
    const float* wk     = (const float*)d_in[4];
    const float* wv     = (const float*)d_in[5];
    const float* wo     = (const float*)d_in[6];
    float* out = (float*)d_out;

    __nv_bfloat16 *xh, *xl, *wh, *wl, *woh, *wol, *ah, *al;
    cudaGetSymbolAddress((void**)&xh,  g_xh);  cudaGetSymbolAddress((void**)&xl,  g_xl);
    cudaGetSymbolAddress((void**)&wh,  g_wh);  cudaGetSymbolAddress((void**)&wl,  g_wl);
    cudaGetSymbolAddress((void**)&woh, g_woh); cudaGetSymbolAddress((void**)&wol, g_wol);
    cudaGetSymbolAddress((void**)&ah,  g_ah);  cudaGetSymbolAddress((void**)&al,  g_al);

    auto blocks = [](size_t n){ return (unsigned)((n / 4 + 255) / 256); };

    split_kernel<<<blocks((size_t)MTOT*HID), 256>>>(hidden, xh, xl, MTOT*HID);
    split_kernel<<<blocks((size_t)4096*4096), 256>>>(wq, wh, wl, 4096*4096);
    split_kernel<<<blocks((size_t)1024*4096), 256>>>(wk, wh + (size_t)4096*4096,
                                                     wl + (size_t)4096*4096, 1024*4096);
    split_kernel<<<blocks((size_t)1024*4096), 256>>>(wv, wh + (size_t)5120*4096,
                                                     wl + (size_t)5120*4096, 1024*4096);
    split_kernel<<<blocks((size_t)HID*HID), 256>>>(wo, woh, wol, HID*HID);

    const int gemm_smem = 1024 + 2 * STAGE_BYTES;
    cudaFuncSetAttribute(gemm_bf16x3<0>, cudaFuncAttributeMaxDynamicSharedMemorySize, gemm_smem);
    cudaFuncSetAttribute(gemm_bf16x3<1>, cudaFuncAttributeMaxDynamicSharedMemorySize, gemm_smem);

    // QKV projection + RoPE -> bf16 hi/lo q/k/v
    gemm_bf16x3<0><<<dim3(48, 32), 256, gemm_smem>>>(xh, xl, wh, wl, cosb, sinb, nullptr);

    // tensor-core flash attention -> bf16 hi/lo attn
    cudaFuncSetAttribute(attn_mma_kernel, cudaFuncAttributeMaxDynamicSharedMemorySize, ATTN_SMEM);
    attn_mma_kernel<<<dim3(SEQ/128, NH, BATCH), 256, ATTN_SMEM>>>();

    // output projection
    gemm_bf16x3<1><<<dim3(32, 32), 256, gemm_smem>>>(ah, al, woh, wol, nullptr, nullptr, out);
}